// round 14
// baseline (speedup 1.0000x reference)
#include <cuda_runtime.h>
#include <cstddef>

// Problem constants
constexpr int Bn = 8;
constexpr int S  = 160;
constexpr int D  = 256;
constexpr int RS = Bn * S;           // 1280 rows of x (flattened)
constexpr int P  = S * (S - 1) / 2;  // 12720 pairs

// GEMM tiling
constexpr int BM = 32, BN = 64, BK = 32;
constexpr int NT = D / BK;                       // 8 k-tiles
constexpr int GEMM_PER_BATCH = (S / BM) * (2 * D / BN);   // 5*8 = 40
constexpr int GT = Bn * GEMM_PER_BATCH;          // 320 gemm tickets

// Expand tiling
constexpr int TI  = 16;
constexpr int TPD = S / TI;                      // 10
constexpr int NTILES = TPD * (TPD + 1) / 2;      // 55
constexpr int EXP_PER_BATCH = NTILES * 2;        // 110 (x2 D-halves)
constexpr int ET = Bn * EXP_PER_BATCH;           // 880
constexpr int NTICK = GT + ET;                   // 1200

// Scratch + sync state (allocation-free __device__ globals)
__device__ float g_xa[RS * D];   // x@Wi + bias
__device__ float g_xb[RS * D];   // x@Wj
__device__ int   g_ticket;
__device__ int   g_done[Bn];

// ---------------------------------------------------------------------------
// helpers
// ---------------------------------------------------------------------------
__device__ __forceinline__ void ffma2(unsigned long long& d,
                                      unsigned long long a,
                                      unsigned long long b) {
    asm("fma.rn.f32x2 %0, %1, %2, %0;" : "+l"(d) : "l"(a), "l"(b));
}
__device__ __forceinline__ unsigned long long dup2(float x) {
    unsigned long long r;
    asm("mov.b64 %0, {%1, %1};" : "=l"(r) : "r"(__float_as_uint(x)));
    return r;
}
__device__ __forceinline__ unsigned long long add2(unsigned long long a,
                                                   unsigned long long b) {
    unsigned long long r;
    asm("add.rn.f32x2 %0, %1, %2;" : "=l"(r) : "l"(a), "l"(b));
    return r;
}
union F2U { unsigned long long u; float2 f; };
__device__ __forceinline__ float2 as_f2(unsigned long long v) { F2U t; t.u = v; return t.f; }

__device__ __forceinline__ int ld_acquire(const int* p) {
    int v;
    asm volatile("ld.acquire.gpu.global.s32 %0, [%1];" : "=r"(v) : "l"(p) : "memory");
    return v;
}
__device__ __forceinline__ void red_release_add(int* p, int v) {
    asm volatile("red.release.gpu.global.add.s32 [%0], %1;" :: "l"(p), "r"(v) : "memory");
}

// Shared memory: gemm tiles and expand staging share the same space
union SmemU {
    struct {
        float xs[2][BK][BM + 2];                 // transposed x tile
        float ws[2][BK][BN + 4];                 // W tile
    } g;                                          // 26112 B
    float4 sb[TI][32];                            // 8192 B
};

// ---------------------------------------------------------------------------
// GEMM tile (R9 inner loop, 256 threads): BM=32 x BN=64, full K=256.
// micro-tile 2 rows x 4 cols: 1 LDS.64 + 1 LDS.128 + 2 MOV + 4 FFMA2 / k-step
// ---------------------------------------------------------------------------
__device__ __forceinline__ void do_gemm(
    int tk, SmemU& sm,
    const float* __restrict__ x, const float* __restrict__ W,
    const float* __restrict__ bias)
{
    const int t  = threadIdx.x;
    const int b  = tk / GEMM_PER_BATCH;
    const int rr = (tk % GEMM_PER_BATCH) >> 3;    // row block 0..4
    const int cb = tk & 7;                         // col block 0..7
    const int r0 = b * S + rr * BM;
    const int half = cb >> 2;                      // 0 -> Wi/g_xa, 1 -> Wj/g_xb
    const int c0 = (cb & 3) * BN;
    const int wbase = half * D;

    const float4* x4 = reinterpret_cast<const float4*>(x);
    const float4* W4 = reinterpret_cast<const float4*>(W);

    // compute mapping: rows 2*ty, 2*ty+1 ; cols 4*tx
    const int ty = t >> 4;   // 0..15
    const int tx = t & 15;   // 0..15

    // staging: x tile 256 f4 -> 1/thread ; W tile 512 f4 -> 2/thread
    const int xrow = t >> 3, xch = t & 7;
    const int wrow = t >> 4, wch = t & 15;

    unsigned long long acc[2][2];
    acc[0][0] = acc[0][1] = acc[1][0] = acc[1][1] = 0ull;

    float4 xv, wv0, wv1;

    // prefetch + store tile 0
    xv  = x4[(size_t)(r0 + xrow) * 64 + xch];
    wv0 = W4[(size_t)(wbase + wrow) * 64 + (c0 >> 2) + wch];
    wv1 = W4[(size_t)(wbase + wrow + 16) * 64 + (c0 >> 2) + wch];

    sm.g.xs[0][xch * 4 + 0][xrow] = xv.x;
    sm.g.xs[0][xch * 4 + 1][xrow] = xv.y;
    sm.g.xs[0][xch * 4 + 2][xrow] = xv.z;
    sm.g.xs[0][xch * 4 + 3][xrow] = xv.w;
    *reinterpret_cast<float4*>(&sm.g.ws[0][wrow][wch * 4])      = wv0;
    *reinterpret_cast<float4*>(&sm.g.ws[0][wrow + 16][wch * 4]) = wv1;
    __syncthreads();

    #pragma unroll 1
    for (int kt = 0; kt < NT; kt++) {
        const int cur = kt & 1;
        const int nxt = cur ^ 1;

        if (kt + 1 < NT) {
            const int kc = (kt + 1) * (BK / 4);
            xv  = x4[(size_t)(r0 + xrow) * 64 + kc + xch];
            wv0 = W4[(size_t)(wbase + (kt + 1) * BK + wrow) * 64 + (c0 >> 2) + wch];
            wv1 = W4[(size_t)(wbase + (kt + 1) * BK + wrow + 16) * 64 + (c0 >> 2) + wch];
        }

        #pragma unroll
        for (int k = 0; k < BK; k++) {
            const float2 a2 = *reinterpret_cast<const float2*>(&sm.g.xs[cur][k][2 * ty]);
            const ulonglong2 wq = *reinterpret_cast<const ulonglong2*>(&sm.g.ws[cur][k][4 * tx]);
            const unsigned long long a0 = dup2(a2.x);
            const unsigned long long a1 = dup2(a2.y);
            ffma2(acc[0][0], a0, wq.x); ffma2(acc[0][1], a0, wq.y);
            ffma2(acc[1][0], a1, wq.x); ffma2(acc[1][1], a1, wq.y);
        }

        if (kt + 1 < NT) {
            sm.g.xs[nxt][xch * 4 + 0][xrow] = xv.x;
            sm.g.xs[nxt][xch * 4 + 1][xrow] = xv.y;
            sm.g.xs[nxt][xch * 4 + 2][xrow] = xv.z;
            sm.g.xs[nxt][xch * 4 + 3][xrow] = xv.w;
            *reinterpret_cast<float4*>(&sm.g.ws[nxt][wrow][wch * 4])      = wv0;
            *reinterpret_cast<float4*>(&sm.g.ws[nxt][wrow + 16][wch * 4]) = wv1;
            __syncthreads();
        }
    }

    // epilogue: bias on Wi half
    const int cc = c0 + 4 * tx;
    float4 bvec = make_float4(0.f, 0.f, 0.f, 0.f);
    if (!half) bvec = *reinterpret_cast<const float4*>(&bias[cc]);
    float* dst = half ? g_xb : g_xa;
    #pragma unroll
    for (int r = 0; r < 2; r++) {
        const int row = r0 + 2 * ty + r;
        const float2 f0 = as_f2(acc[r][0]);
        const float2 f1 = as_f2(acc[r][1]);
        *reinterpret_cast<float4*>(&dst[(size_t)row * D + cc]) =
            make_float4(f0.x + bvec.x, f0.y + bvec.y, f1.x + bvec.z, f1.y + bvec.w);
    }

    // publish: all stores fenced, then one release-add on the batch flag
    __threadfence();
    __syncthreads();
    if (t == 0) red_release_add(&g_done[b], 1);
}

// ---------------------------------------------------------------------------
// Expand tile (R9 structure, 256 threads = 8 warps)
// ---------------------------------------------------------------------------
__device__ __forceinline__ void do_expand(int e, SmemU& sm, float* __restrict__ out)
{
    const int b   = e / EXP_PER_BATCH;
    const int rm  = e % EXP_PER_BATCH;
    const int til = rm >> 1;
    const int h   = rm & 1;

    const int tid = threadIdx.x;

    // wait for this batch's GEMM tiles
    if (tid == 0) {
        while (ld_acquire(&g_done[b]) < GEMM_PER_BATCH) __nanosleep(64);
    }
    __syncthreads();

    int rem = til, ti = 0;
    while (rem >= TPD - ti) { rem -= TPD - ti; ti++; }
    const int tj = ti + rem;

    const int i0 = ti * TI;
    const int j0 = tj * TI;
    const int warp = tid >> 5;
    const int lane = tid & 31;

    const float4* xa4 = reinterpret_cast<const float4*>(g_xa);
    const float4* xb4 = reinterpret_cast<const float4*>(g_xb);

    #pragma unroll
    for (int q = 0; q < 2; q++) {
        const int k = tid + q * 256;
        const int r = k >> 5, c = k & 31;
        sm.sb[r][c] = xb4[(size_t)(b * S + j0 + r) * 64 + h * 32 + c];
    }

    const int ia = i0 + 2 * warp;
    const int ib = ia + 1;
    const float4 A0 = xa4[(size_t)(b * S + ia) * 64 + h * 32 + lane];
    const float4 A1 = xa4[(size_t)(b * S + ib) * 64 + h * 32 + lane];
    F2U a0lo, a0hi, a1lo, a1hi;
    a0lo.f = make_float2(A0.x, A0.y); a0hi.f = make_float2(A0.z, A0.w);
    a1lo.f = make_float2(A1.x, A1.y); a1hi.f = make_float2(A1.z, A1.w);

    __syncthreads();

    const int p0 = ((2 * S - 1 - ia) * ia) / 2 + j0 - ia - 1;
    const int p1 = ((2 * S - 1 - ib) * ib) / 2 + j0 - ib - 1;

    float4* out4 = reinterpret_cast<float4*>(out);
    float4* o0 = out4 + ((size_t)b * P + p0) * 64 + h * 32 + lane;
    float4* o1 = out4 + ((size_t)b * P + p1) * 64 + h * 32 + lane;

    #pragma unroll
    for (int jj = 0; jj < TI; jj++) {
        const float4 v = sm.sb[jj][lane];
        F2U vlo, vhi;
        vlo.f = make_float2(v.x, v.y);
        vhi.f = make_float2(v.z, v.w);
        const int j = j0 + jj;

        if (j > ia) {
            F2U rlo, rhi;
            rlo.u = add2(a0lo.u, vlo.u);
            rhi.u = add2(a0hi.u, vhi.u);
            o0[(size_t)jj * 64] = make_float4(rlo.f.x, rlo.f.y, rhi.f.x, rhi.f.y);
        }
        if (j > ib) {
            F2U rlo, rhi;
            rlo.u = add2(a1lo.u, vlo.u);
            rhi.u = add2(a1hi.u, vhi.u);
            o1[(size_t)jj * 64] = make_float4(rlo.f.x, rlo.f.y, rhi.f.x, rhi.f.y);
        }
    }
}

// ---------------------------------------------------------------------------
// init: reset ticket + flags each replay (graph-deterministic)
// ---------------------------------------------------------------------------
__global__ void init_kernel()
{
    if (threadIdx.x == 0) g_ticket = 0;
    if (threadIdx.x < Bn) g_done[threadIdx.x] = 0;
}

// ---------------------------------------------------------------------------
// fused persistent kernel: atomic ticket queue over [gemm tiles | expand tiles]
// ---------------------------------------------------------------------------
__global__ __launch_bounds__(256) void fused_kernel(
    const float* __restrict__ x,
    const float* __restrict__ W,
    const float* __restrict__ bias,
    float* __restrict__ out)
{
    __shared__ SmemU sm;
    __shared__ int s_ticket;

    for (;;) {
        __syncthreads();   // protect smem + s_ticket reuse across items
        if (threadIdx.x == 0) s_ticket = atomicAdd(&g_ticket, 1);
        __syncthreads();
        const int tk = s_ticket;
        if (tk >= NTICK) return;

        if (tk < GT) do_gemm(tk, sm, x, W, bias);
        else         do_expand(tk - GT, sm, out);
    }
}

// ---------------------------------------------------------------------------
extern "C" void kernel_launch(void* const* d_in, const int* in_sizes, int n_in,
                              void* d_out, int out_size)
{
    const float* x    = (const float*)d_in[0];   // (8,160,256) f32
    const float* W    = (const float*)d_in[1];   // (512,256)   f32
    const float* bias = (const float*)d_in[2];   // (256,)      f32
    float* out = (float*)d_out;                  // (8,12720,256) f32

    init_kernel<<<1, 32>>>();
    fused_kernel<<<592, 256>>>(x, W, bias, out);
}

// round 16
// speedup vs baseline: 1.1834x; 1.1834x over previous
#include <cuda_runtime.h>
#include <cstddef>
#include <cstdint>

// Problem constants
constexpr int Bn = 8;
constexpr int S  = 160;
constexpr int D  = 256;
constexpr int RS = Bn * S;           // 1280 rows of x (flattened)
constexpr int P  = S * (S - 1) / 2;  // 12720 pairs

// Scratch (allocation-free __device__ globals)
__device__ float g_xa[RS * D];       // x@Wi + bias
__device__ float g_xb[RS * D];       // x@Wj
__device__ float g_xhi[RS * D];      // tf32 split of x
__device__ float g_xlo[RS * D];
__device__ float g_whi[2 * D * D];   // tf32 split of W
__device__ float g_wlo[2 * D * D];

// ---------------------------------------------------------------------------
// helpers
// ---------------------------------------------------------------------------
__device__ __forceinline__ unsigned long long add2(unsigned long long a,
                                                   unsigned long long b) {
    unsigned long long r;
    asm("add.rn.f32x2 %0, %1, %2;" : "=l"(r) : "l"(a), "l"(b));
    return r;
}
union F2U { unsigned long long u; float2 f; };

__device__ __forceinline__ void tf32_split(float v, float& hi, float& lo) {
    uint32_t h;
    asm("cvt.rna.tf32.f32 %0, %1;" : "=r"(h) : "f"(v));
    hi = __uint_as_float(h);
    uint32_t l;
    asm("cvt.rna.tf32.f32 %0, %1;" : "=r"(l) : "f"(v - hi));
    lo = __uint_as_float(l);
}

__device__ __forceinline__ void mma_tf32(
    float& d0, float& d1, float& d2, float& d3,
    float a0, float a1, float a2, float a3,
    float b0, float b1)
{
    asm volatile(
        "mma.sync.aligned.m16n8k8.row.col.f32.tf32.tf32.f32 "
        "{%0,%1,%2,%3}, {%4,%5,%6,%7}, {%8,%9}, {%0,%1,%2,%3};"
        : "+f"(d0), "+f"(d1), "+f"(d2), "+f"(d3)
        : "r"(__float_as_uint(a0)), "r"(__float_as_uint(a1)),
          "r"(__float_as_uint(a2)), "r"(__float_as_uint(a3)),
          "r"(__float_as_uint(b0)), "r"(__float_as_uint(b1)));
}

// ---------------------------------------------------------------------------
// Kernel 0: tf32 hi/lo split of x and W (once per replay, ~0.5us)
// ---------------------------------------------------------------------------
constexpr int XF4 = RS * D / 4;          // 81920
constexpr int WF4 = 2 * D * D / 4;       // 32768
constexpr int TOTF4 = XF4 + WF4;         // 114688

__global__ __launch_bounds__(256) void split_kernel(
    const float* __restrict__ x, const float* __restrict__ W)
{
    const int idx = blockIdx.x * 256 + threadIdx.x;
    float4 v;
    float4* hid;
    float4* lod;
    int o;
    if (idx < XF4) {
        v = reinterpret_cast<const float4*>(x)[idx];
        hid = reinterpret_cast<float4*>(g_xhi);
        lod = reinterpret_cast<float4*>(g_xlo);
        o = idx;
    } else {
        o = idx - XF4;
        v = reinterpret_cast<const float4*>(W)[o];
        hid = reinterpret_cast<float4*>(g_whi);
        lod = reinterpret_cast<float4*>(g_wlo);
    }
    float4 h, l;
    tf32_split(v.x, h.x, l.x);
    tf32_split(v.y, h.y, l.y);
    tf32_split(v.z, h.z, l.z);
    tf32_split(v.w, h.w, l.w);
    hid[o] = h;
    lod[o] = l;
}

// ---------------------------------------------------------------------------
// Kernel 1: 3xTF32 tensor-core dual GEMM.
// C(1280 x 512) = X(1280 x 256) . [Wi | Wj], via mma.sync.m16n8k8 tf32 with
// hi/lo split: D += Ahi.Bhi + Alo.Bhi + Ahi.Blo  (error ~2^-22, fp32-class).
// BM=64, BN=32, BK=32, 128 threads (4 warps, warp w -> rows 16w..16w+15).
// smem row stride 44 floats: A-frag banks (12g+k) and B-frag banks (12k+n)
// both cover all 32 banks -> conflict-free; STS.128 staging, no transpose.
// Grid (20, 16) = 320 CTAs.
// ---------------------------------------------------------------------------
constexpr int GBM = 64, GBN = 32, GBK = 32;
constexpr int GNT = D / GBK;   // 8 k-tiles
constexpr int XPAD = 44;       // padded row stride (floats)

__global__ __launch_bounds__(128) void mma_gemm_kernel(
    const float* __restrict__ bias)
{
    __shared__ float sxh[GBM * XPAD];   // X hi tile [m][k]
    __shared__ float sxl[GBM * XPAD];   // X lo tile
    __shared__ float swh[GBK * XPAD];   // W hi tile [k][n]
    __shared__ float swl[GBK * XPAD];   // W lo tile

    const int t  = threadIdx.x;
    const int r0 = blockIdx.x * GBM;
    const int by = blockIdx.y;
    const int half = by >> 3;            // 0 -> Wi/g_xa, 1 -> Wj/g_xb
    const int c0 = (by & 7) * GBN;       // col within half
    const int wr0 = half * D;            // W row base

    const float4* xh4 = reinterpret_cast<const float4*>(g_xhi);
    const float4* xl4 = reinterpret_cast<const float4*>(g_xlo);
    const float4* wh4 = reinterpret_cast<const float4*>(g_whi);
    const float4* wl4 = reinterpret_cast<const float4*>(g_wlo);

    // staging mapping
    const int xrow = t >> 3;             // 0..15 (+16q)
    const int xch  = t & 7;              // f4 chunk within 32-float k-row
    // W tile: 512 floats*... 32x32 = 256 f4 per buf, 2 per thread (k=t>>3, +16)

    // compute mapping
    const int w    = t >> 5;             // warp 0..3 -> rows 16w..
    const int lane = t & 31;
    const int g    = lane >> 2;          // 0..7
    const int c    = lane & 3;           // 0..3
    const int m0s  = (16 * w + g) * XPAD;     // smem row offset, row m0
    const int m1s  = m0s + 8 * XPAD;          // row m0+8

    float acc[4][4];
    #pragma unroll
    for (int n = 0; n < 4; n++)
        #pragma unroll
        for (int i = 0; i < 4; i++) acc[n][i] = 0.0f;

    float4 pxh[4], pxl[4], pwh[2], pwl[2];

    // prefetch tile 0
    #pragma unroll
    for (int q = 0; q < 4; q++) {
        pxh[q] = xh4[(size_t)(r0 + xrow + 16 * q) * 64 + xch];
        pxl[q] = xl4[(size_t)(r0 + xrow + 16 * q) * 64 + xch];
    }
    #pragma unroll
    for (int q = 0; q < 2; q++) {
        pwh[q] = wh4[(size_t)(wr0 + xrow + 16 * q) * 64 + (c0 >> 2) + xch];
        pwl[q] = wl4[(size_t)(wr0 + xrow + 16 * q) * 64 + (c0 >> 2) + xch];
    }

    #pragma unroll 1
    for (int kt = 0; kt < GNT; kt++) {
        __syncthreads();   // prior compute done reading smem
        #pragma unroll
        for (int q = 0; q < 4; q++) {
            *reinterpret_cast<float4*>(&sxh[(xrow + 16 * q) * XPAD + xch * 4]) = pxh[q];
            *reinterpret_cast<float4*>(&sxl[(xrow + 16 * q) * XPAD + xch * 4]) = pxl[q];
        }
        #pragma unroll
        for (int q = 0; q < 2; q++) {
            *reinterpret_cast<float4*>(&swh[(xrow + 16 * q) * XPAD + xch * 4]) = pwh[q];
            *reinterpret_cast<float4*>(&swl[(xrow + 16 * q) * XPAD + xch * 4]) = pwl[q];
        }
        __syncthreads();

        if (kt + 1 < GNT) {  // prefetch next tile (hidden under compute)
            const int kc = (kt + 1) * 8;
            #pragma unroll
            for (int q = 0; q < 4; q++) {
                pxh[q] = xh4[(size_t)(r0 + xrow + 16 * q) * 64 + kc + xch];
                pxl[q] = xl4[(size_t)(r0 + xrow + 16 * q) * 64 + kc + xch];
            }
            #pragma unroll
            for (int q = 0; q < 2; q++) {
                pwh[q] = wh4[(size_t)(wr0 + (kt + 1) * GBK + xrow + 16 * q) * 64 + (c0 >> 2) + xch];
                pwl[q] = wl4[(size_t)(wr0 + (kt + 1) * GBK + xrow + 16 * q) * 64 + (c0 >> 2) + xch];
            }
        }

        // compute: 4 k8-chunks x 4 n8-tiles x 3 splits
        #pragma unroll
        for (int q = 0; q < 4; q++) {
            const int k0 = 8 * q;
            const float ah0 = sxh[m0s + k0 + c];
            const float ah1 = sxh[m1s + k0 + c];
            const float ah2 = sxh[m0s + k0 + 4 + c];
            const float ah3 = sxh[m1s + k0 + 4 + c];
            const float al0 = sxl[m0s + k0 + c];
            const float al1 = sxl[m1s + k0 + c];
            const float al2 = sxl[m0s + k0 + 4 + c];
            const float al3 = sxl[m1s + k0 + 4 + c];
            #pragma unroll
            for (int n = 0; n < 4; n++) {
                const int nb = 8 * n + g;
                const float bh0 = swh[(k0 + c) * XPAD + nb];
                const float bh1 = swh[(k0 + 4 + c) * XPAD + nb];
                const float bl0 = swl[(k0 + c) * XPAD + nb];
                const float bl1 = swl[(k0 + 4 + c) * XPAD + nb];
                mma_tf32(acc[n][0], acc[n][1], acc[n][2], acc[n][3],
                         ah0, ah1, ah2, ah3, bh0, bh1);
                mma_tf32(acc[n][0], acc[n][1], acc[n][2], acc[n][3],
                         al0, al1, al2, al3, bh0, bh1);
                mma_tf32(acc[n][0], acc[n][1], acc[n][2], acc[n][3],
                         ah0, ah1, ah2, ah3, bl0, bl1);
            }
        }
    }

    // epilogue: c0/c1 -> row, c2/c3 -> row+8; bias on Wi half
    float* dst = half ? g_xb : g_xa;
    const int row0 = r0 + 16 * w + g;
    #pragma unroll
    for (int n = 0; n < 4; n++) {
        const int col = c0 + 8 * n + 2 * c;
        float2 bv = make_float2(0.f, 0.f);
        if (!half) bv = *reinterpret_cast<const float2*>(&bias[col]);
        *reinterpret_cast<float2*>(&dst[(size_t)row0 * D + col]) =
            make_float2(acc[n][0] + bv.x, acc[n][1] + bv.y);
        *reinterpret_cast<float2*>(&dst[(size_t)(row0 + 8) * D + col]) =
            make_float2(acc[n][2] + bv.x, acc[n][3] + bv.y);
    }
}

// ---------------------------------------------------------------------------
// Kernel 2: pairwise expansion (R9 verbatim; stable 18.2-18.6us)
// ---------------------------------------------------------------------------
constexpr int TI  = 16;
constexpr int TPD = S / TI;                      // 10
constexpr int NTILES = TPD * (TPD + 1) / 2;      // 55

__global__ __launch_bounds__(256) void expand_kernel(float* __restrict__ out)
{
    __shared__ float4 sb[TI][32];

    int rem = blockIdx.x, ti = 0;
    while (rem >= TPD - ti) { rem -= TPD - ti; ti++; }
    const int tj = ti + rem;

    const int b   = blockIdx.y;
    const int h   = blockIdx.z;   // D half
    const int i0  = ti * TI;
    const int j0  = tj * TI;
    const int tid = threadIdx.x;
    const int warp = tid >> 5;
    const int lane = tid & 31;

    const float4* xa4 = reinterpret_cast<const float4*>(g_xa);
    const float4* xb4 = reinterpret_cast<const float4*>(g_xb);

    #pragma unroll
    for (int q = 0; q < 2; q++) {
        const int k = tid + q * 256;
        const int r = k >> 5, c = k & 31;
        sb[r][c] = xb4[(size_t)(b * S + j0 + r) * 64 + h * 32 + c];
    }

    const int ia = i0 + 2 * warp;
    const int ib = ia + 1;
    const float4 A0 = xa4[(size_t)(b * S + ia) * 64 + h * 32 + lane];
    const float4 A1 = xa4[(size_t)(b * S + ib) * 64 + h * 32 + lane];
    F2U a0lo, a0hi, a1lo, a1hi;
    a0lo.f = make_float2(A0.x, A0.y); a0hi.f = make_float2(A0.z, A0.w);
    a1lo.f = make_float2(A1.x, A1.y); a1hi.f = make_float2(A1.z, A1.w);

    __syncthreads();

    const int p0 = ((2 * S - 1 - ia) * ia) / 2 + j0 - ia - 1;
    const int p1 = ((2 * S - 1 - ib) * ib) / 2 + j0 - ib - 1;

    float4* out4 = reinterpret_cast<float4*>(out);
    float4* o0 = out4 + ((size_t)b * P + p0) * 64 + h * 32 + lane;
    float4* o1 = out4 + ((size_t)b * P + p1) * 64 + h * 32 + lane;

    #pragma unroll
    for (int jj = 0; jj < TI; jj++) {
        const float4 v = sb[jj][lane];
        F2U vlo, vhi;
        vlo.f = make_float2(v.x, v.y);
        vhi.f = make_float2(v.z, v.w);
        const int j = j0 + jj;

        if (j > ia) {
            F2U rlo, rhi;
            rlo.u = add2(a0lo.u, vlo.u);
            rhi.u = add2(a0hi.u, vhi.u);
            o0[(size_t)jj * 64] = make_float4(rlo.f.x, rlo.f.y, rhi.f.x, rhi.f.y);
        }
        if (j > ib) {
            F2U rlo, rhi;
            rlo.u = add2(a1lo.u, vlo.u);
            rhi.u = add2(a1hi.u, vhi.u);
            o1[(size_t)jj * 64] = make_float4(rlo.f.x, rlo.f.y, rhi.f.x, rhi.f.y);
        }
    }
}

// ---------------------------------------------------------------------------
extern "C" void kernel_launch(void* const* d_in, const int* in_sizes, int n_in,
                              void* d_out, int out_size)
{
    const float* x    = (const float*)d_in[0];   // (8,160,256) f32
    const float* W    = (const float*)d_in[1];   // (512,256)   f32
    const float* bias = (const float*)d_in[2];   // (256,)      f32
    float* out = (float*)d_out;                  // (8,12720,256) f32

    split_kernel<<<TOTF4 / 256, 256>>>(x, W);
    mma_gemm_kernel<<<dim3(RS / GBM, 2 * D / GBN), 128>>>(bias);
    expand_kernel<<<dim3(NTILES, Bn, 2), 256>>>(out);
}

// round 17
// speedup vs baseline: 1.1907x; 1.0062x over previous
#include <cuda_runtime.h>
#include <cstddef>
#include <cstdint>

// Problem constants
constexpr int Bn = 8;
constexpr int S  = 160;
constexpr int D  = 256;
constexpr int RS = Bn * S;           // 1280 rows of x (flattened)
constexpr int P  = S * (S - 1) / 2;  // 12720 pairs

// Scratch (allocation-free __device__ globals)
__device__ float g_xa[RS * D];       // x@Wi + bias
__device__ float g_xb[RS * D];       // x@Wj
__device__ float g_xhi[RS * D];      // tf32 split of x
__device__ float g_xlo[RS * D];
__device__ float g_whi[2 * D * D];   // tf32 split of W
__device__ float g_wlo[2 * D * D];

// ---------------------------------------------------------------------------
// helpers
// ---------------------------------------------------------------------------
__device__ __forceinline__ unsigned long long add2(unsigned long long a,
                                                   unsigned long long b) {
    unsigned long long r;
    asm("add.rn.f32x2 %0, %1, %2;" : "=l"(r) : "l"(a), "l"(b));
    return r;
}
union F2U { unsigned long long u; float2 f; };

__device__ __forceinline__ void tf32_split(float v, float& hi, float& lo) {
    uint32_t h;
    asm("cvt.rna.tf32.f32 %0, %1;" : "=r"(h) : "f"(v));
    hi = __uint_as_float(h);
    uint32_t l;
    asm("cvt.rna.tf32.f32 %0, %1;" : "=r"(l) : "f"(v - hi));
    lo = __uint_as_float(l);
}

__device__ __forceinline__ void mma_tf32(
    float& d0, float& d1, float& d2, float& d3,
    float a0, float a1, float a2, float a3,
    float b0, float b1)
{
    asm volatile(
        "mma.sync.aligned.m16n8k8.row.col.f32.tf32.tf32.f32 "
        "{%0,%1,%2,%3}, {%4,%5,%6,%7}, {%8,%9}, {%0,%1,%2,%3};"
        : "+f"(d0), "+f"(d1), "+f"(d2), "+f"(d3)
        : "r"(__float_as_uint(a0)), "r"(__float_as_uint(a1)),
          "r"(__float_as_uint(a2)), "r"(__float_as_uint(a3)),
          "r"(__float_as_uint(b0)), "r"(__float_as_uint(b1)));
}

// ---------------------------------------------------------------------------
// Kernel 0: tf32 hi/lo split of x and W. 2 float4/thread, independent chains.
// ---------------------------------------------------------------------------
constexpr int XF4 = RS * D / 4;          // 81920
constexpr int WF4 = 2 * D * D / 4;       // 32768
constexpr int TOTF4 = XF4 + WF4;         // 114688
constexpr int SPLIT_BLOCKS = TOTF4 / 512;  // 224

__device__ __forceinline__ void split_one(int idx,
    const float* __restrict__ x, const float* __restrict__ W)
{
    float4 v;
    float4* hid;
    float4* lod;
    int o;
    if (idx < XF4) {
        v = reinterpret_cast<const float4*>(x)[idx];
        hid = reinterpret_cast<float4*>(g_xhi);
        lod = reinterpret_cast<float4*>(g_xlo);
        o = idx;
    } else {
        o = idx - XF4;
        v = reinterpret_cast<const float4*>(W)[o];
        hid = reinterpret_cast<float4*>(g_whi);
        lod = reinterpret_cast<float4*>(g_wlo);
    }
    float4 h, l;
    tf32_split(v.x, h.x, l.x);
    tf32_split(v.y, h.y, l.y);
    tf32_split(v.z, h.z, l.z);
    tf32_split(v.w, h.w, l.w);
    hid[o] = h;
    lod[o] = l;
}

__global__ __launch_bounds__(256) void split_kernel(
    const float* __restrict__ x, const float* __restrict__ W)
{
    const int base = blockIdx.x * 512 + threadIdx.x;
    split_one(base, x, W);
    split_one(base + 256, x, W);
}

// ---------------------------------------------------------------------------
// Kernel 1: 3xTF32 tensor-core dual GEMM, light warps for occupancy.
// C(1280 x 512) = X . [Wi | Wj] via mma.sync.m16n8k8 tf32, hi/lo split:
//   D += Ahi.Bhi + Alo.Bhi + Ahi.Blo   (error ~2^-22)
// BM=32, BN=32, BK=32, 128 threads = 4 warps, warp tile m16 x n16
// (warp (wr,wc): rows 16*wr.., cols 16*wc.., 2 n8-tiles).
// Grid (40,16) = 640 blocks -> 4.3 blocks/SM, 4.3 warps/SMSP.
// smem row stride 44: A-frag banks (12g+c) all-distinct, B-frag 2-way max.
// ---------------------------------------------------------------------------
constexpr int GBM = 32, GBN = 32, GBK = 32;
constexpr int GNT = D / GBK;   // 8 k-tiles
constexpr int XPAD = 44;       // padded row stride (floats)

__global__ __launch_bounds__(128) void mma_gemm_kernel(
    const float* __restrict__ bias)
{
    __shared__ float sxh[GBM * XPAD];   // X hi tile [m][k]
    __shared__ float sxl[GBM * XPAD];   // X lo tile
    __shared__ float swh[GBK * XPAD];   // W hi tile [k][n]
    __shared__ float swl[GBK * XPAD];   // W lo tile

    const int t  = threadIdx.x;
    const int r0 = blockIdx.x * GBM;
    const int by = blockIdx.y;
    const int half = by >> 3;            // 0 -> Wi/g_xa, 1 -> Wj/g_xb
    const int c0 = (by & 7) * GBN;       // col within half
    const int wr0 = half * D;            // W row base

    const float4* xh4 = reinterpret_cast<const float4*>(g_xhi);
    const float4* xl4 = reinterpret_cast<const float4*>(g_xlo);
    const float4* wh4 = reinterpret_cast<const float4*>(g_whi);
    const float4* wl4 = reinterpret_cast<const float4*>(g_wlo);

    // staging mapping: 256 f4 per (hi|lo)x(x|w) tile -> 2 rows per thread
    const int srow = t >> 3;             // 0..15 (and +16)
    const int sch  = t & 7;              // f4 chunk in 32-float k-row

    // compute mapping: warp (wr, wc), m16 x n16
    const int w    = t >> 5;
    const int wr   = w >> 1;             // 0..1 -> rows 16*wr..
    const int wc   = w & 1;              // 0..1 -> cols 16*wc..
    const int lane = t & 31;
    const int g    = lane >> 2;          // 0..7
    const int c    = lane & 3;           // 0..3
    const int m0s  = (16 * wr + g) * XPAD;
    const int m1s  = m0s + 8 * XPAD;

    float acc[2][4];
    #pragma unroll
    for (int n = 0; n < 2; n++)
        #pragma unroll
        for (int i = 0; i < 4; i++) acc[n][i] = 0.0f;

    float4 pxh[2], pxl[2], pwh[2], pwl[2];

    // prefetch tile 0
    #pragma unroll
    for (int q = 0; q < 2; q++) {
        pxh[q] = xh4[(size_t)(r0 + srow + 16 * q) * 64 + sch];
        pxl[q] = xl4[(size_t)(r0 + srow + 16 * q) * 64 + sch];
        pwh[q] = wh4[(size_t)(wr0 + srow + 16 * q) * 64 + (c0 >> 2) + sch];
        pwl[q] = wl4[(size_t)(wr0 + srow + 16 * q) * 64 + (c0 >> 2) + sch];
    }

    #pragma unroll 1
    for (int kt = 0; kt < GNT; kt++) {
        __syncthreads();   // prior compute done reading smem
        #pragma unroll
        for (int q = 0; q < 2; q++) {
            *reinterpret_cast<float4*>(&sxh[(srow + 16 * q) * XPAD + sch * 4]) = pxh[q];
            *reinterpret_cast<float4*>(&sxl[(srow + 16 * q) * XPAD + sch * 4]) = pxl[q];
            *reinterpret_cast<float4*>(&swh[(srow + 16 * q) * XPAD + sch * 4]) = pwh[q];
            *reinterpret_cast<float4*>(&swl[(srow + 16 * q) * XPAD + sch * 4]) = pwl[q];
        }
        __syncthreads();

        if (kt + 1 < GNT) {  // prefetch next tile (hidden under compute)
            const int kc = (kt + 1) * 8;
            #pragma unroll
            for (int q = 0; q < 2; q++) {
                pxh[q] = xh4[(size_t)(r0 + srow + 16 * q) * 64 + kc + sch];
                pxl[q] = xl4[(size_t)(r0 + srow + 16 * q) * 64 + kc + sch];
                pwh[q] = wh4[(size_t)(wr0 + (kt + 1) * GBK + srow + 16 * q) * 64 + (c0 >> 2) + sch];
                pwl[q] = wl4[(size_t)(wr0 + (kt + 1) * GBK + srow + 16 * q) * 64 + (c0 >> 2) + sch];
            }
        }

        // compute: 4 k8-chunks x 2 n8-tiles x 3 splits
        #pragma unroll
        for (int q = 0; q < 4; q++) {
            const int k0 = 8 * q;
            const float ah0 = sxh[m0s + k0 + c];
            const float ah1 = sxh[m1s + k0 + c];
            const float ah2 = sxh[m0s + k0 + 4 + c];
            const float ah3 = sxh[m1s + k0 + 4 + c];
            const float al0 = sxl[m0s + k0 + c];
            const float al1 = sxl[m1s + k0 + c];
            const float al2 = sxl[m0s + k0 + 4 + c];
            const float al3 = sxl[m1s + k0 + 4 + c];
            #pragma unroll
            for (int n = 0; n < 2; n++) {
                const int nb = 16 * wc + 8 * n + g;
                const float bh0 = swh[(k0 + c) * XPAD + nb];
                const float bh1 = swh[(k0 + 4 + c) * XPAD + nb];
                const float bl0 = swl[(k0 + c) * XPAD + nb];
                const float bl1 = swl[(k0 + 4 + c) * XPAD + nb];
                mma_tf32(acc[n][0], acc[n][1], acc[n][2], acc[n][3],
                         ah0, ah1, ah2, ah3, bh0, bh1);
                mma_tf32(acc[n][0], acc[n][1], acc[n][2], acc[n][3],
                         al0, al1, al2, al3, bh0, bh1);
                mma_tf32(acc[n][0], acc[n][1], acc[n][2], acc[n][3],
                         ah0, ah1, ah2, ah3, bl0, bl1);
            }
        }
    }

    // epilogue: c0/c1 -> row, c2/c3 -> row+8; bias on Wi half
    float* dst = half ? g_xb : g_xa;
    const int row0 = r0 + 16 * wr + g;
    #pragma unroll
    for (int n = 0; n < 2; n++) {
        const int col = c0 + 16 * wc + 8 * n + 2 * c;
        float2 bv = make_float2(0.f, 0.f);
        if (!half) bv = *reinterpret_cast<const float2*>(&bias[col]);
        *reinterpret_cast<float2*>(&dst[(size_t)row0 * D + col]) =
            make_float2(acc[n][0] + bv.x, acc[n][1] + bv.y);
        *reinterpret_cast<float2*>(&dst[(size_t)(row0 + 8) * D + col]) =
            make_float2(acc[n][2] + bv.x, acc[n][3] + bv.y);
    }
}

// ---------------------------------------------------------------------------
// Kernel 2: pairwise expansion (R9 verbatim; stable 18.2-18.6us)
// ---------------------------------------------------------------------------
constexpr int TI  = 16;
constexpr int TPD = S / TI;                      // 10
constexpr int NTILES = TPD * (TPD + 1) / 2;      // 55

__global__ __launch_bounds__(256) void expand_kernel(float* __restrict__ out)
{
    __shared__ float4 sb[TI][32];

    int rem = blockIdx.x, ti = 0;
    while (rem >= TPD - ti) { rem -= TPD - ti; ti++; }
    const int tj = ti + rem;

    const int b   = blockIdx.y;
    const int h   = blockIdx.z;   // D half
    const int i0  = ti * TI;
    const int j0  = tj * TI;
    const int tid = threadIdx.x;
    const int warp = tid >> 5;
    const int lane = tid & 31;

    const float4* xa4 = reinterpret_cast<const float4*>(g_xa);
    const float4* xb4 = reinterpret_cast<const float4*>(g_xb);

    #pragma unroll
    for (int q = 0; q < 2; q++) {
        const int k = tid + q * 256;
        const int r = k >> 5, c = k & 31;
        sb[r][c] = xb4[(size_t)(b * S + j0 + r) * 64 + h * 32 + c];
    }

    const int ia = i0 + 2 * warp;
    const int ib = ia + 1;
    const float4 A0 = xa4[(size_t)(b * S + ia) * 64 + h * 32 + lane];
    const float4 A1 = xa4[(size_t)(b * S + ib) * 64 + h * 32 + lane];
    F2U a0lo, a0hi, a1lo, a1hi;
    a0lo.f = make_float2(A0.x, A0.y); a0hi.f = make_float2(A0.z, A0.w);
    a1lo.f = make_float2(A1.x, A1.y); a1hi.f = make_float2(A1.z, A1.w);

    __syncthreads();

    const int p0 = ((2 * S - 1 - ia) * ia) / 2 + j0 - ia - 1;
    const int p1 = ((2 * S - 1 - ib) * ib) / 2 + j0 - ib - 1;

    float4* out4 = reinterpret_cast<float4*>(out);
    float4* o0 = out4 + ((size_t)b * P + p0) * 64 + h * 32 + lane;
    float4* o1 = out4 + ((size_t)b * P + p1) * 64 + h * 32 + lane;

    #pragma unroll
    for (int jj = 0; jj < TI; jj++) {
        const float4 v = sb[jj][lane];
        F2U vlo, vhi;
        vlo.f = make_float2(v.x, v.y);
        vhi.f = make_float2(v.z, v.w);
        const int j = j0 + jj;

        if (j > ia) {
            F2U rlo, rhi;
            rlo.u = add2(a0lo.u, vlo.u);
            rhi.u = add2(a0hi.u, vhi.u);
            o0[(size_t)jj * 64] = make_float4(rlo.f.x, rlo.f.y, rhi.f.x, rhi.f.y);
        }
        if (j > ib) {
            F2U rlo, rhi;
            rlo.u = add2(a1lo.u, vlo.u);
            rhi.u = add2(a1hi.u, vhi.u);
            o1[(size_t)jj * 64] = make_float4(rlo.f.x, rlo.f.y, rhi.f.x, rhi.f.y);
        }
    }
}

// ---------------------------------------------------------------------------
extern "C" void kernel_launch(void* const* d_in, const int* in_sizes, int n_in,
                              void* d_out, int out_size)
{
    const float* x    = (const float*)d_in[0];   // (8,160,256) f32
    const float* W    = (const float*)d_in[1];   // (512,256)   f32
    const float* bias = (const float*)d_in[2];   // (256,)      f32
    float* out = (float*)d_out;                  // (8,12720,256) f32

    split_kernel<<<SPLIT_BLOCKS, 256>>>(x, W);
    mma_gemm_kernel<<<dim3(RS / GBM, 2 * D / GBN), 128>>>(bias);
    expand_kernel<<<dim3(NTILES, Bn, 2), 256>>>(out);
}